// round 1
// baseline (speedup 1.0000x reference)
#include <cuda_runtime.h>
#include <cuda_bf16.h>

// SE block: B=32, H=W=56 (HW=3136), C=256, R=16
#define HW    3136
#define CCH   256
#define NB    32
#define NS    49      // HW chunks in pool pass
#define CHUNK 64      // hw rows per pool block (49*64 = 3136)

// Scratch (allocation-free rule: __device__ globals)
__device__ float g_partial[NS * NB * CCH];   // [s][b][c] partial sums
__device__ float g_gate[NB * CCH];           // sigmoid gate

// ---------------- Pass 1: partial pool ----------------
// grid (NS, NB), 256 threads. Thread t: c4 = t&63 (float4 channel group),
// ho = t>>6 (hw sub-offset 0..3). Each thread accumulates 16 float4 loads.
__global__ void __launch_bounds__(256) k_pool(const float* __restrict__ x) {
    const int s = blockIdx.x, b = blockIdx.y;
    const int t = threadIdx.x;
    const int c4 = t & 63;
    const int ho = t >> 6;

    const float4* xp = reinterpret_cast<const float4*>(x)
                     + ((size_t)b * HW + (size_t)s * CHUNK + ho) * (CCH / 4) + c4;

    float4 acc = make_float4(0.f, 0.f, 0.f, 0.f);
#pragma unroll
    for (int k = 0; k < CHUNK; k += 4) {
        float4 v = xp[(size_t)k * (CCH / 4)];
        acc.x += v.x; acc.y += v.y; acc.z += v.z; acc.w += v.w;
    }

    __shared__ float4 sm[256];
    sm[t] = acc;
    __syncthreads();

    if (t < 64) {
        float4 a = sm[t], b2_ = sm[t + 64], c2 = sm[t + 128], d2 = sm[t + 192];
        float4 r = make_float4(a.x + b2_.x + c2.x + d2.x,
                               a.y + b2_.y + c2.y + d2.y,
                               a.z + b2_.z + c2.z + d2.z,
                               a.w + b2_.w + c2.w + d2.w);
        reinterpret_cast<float4*>(g_partial)[((size_t)s * NB + b) * (CCH / 4) + t] = r;
    }
}

// ---------------- Pass 2: finish mean + excitation MLP ----------------
// grid NB, 256 threads (one block per batch element).
__global__ void __launch_bounds__(256) k_mlp(const float* __restrict__ w1,
                                             const float* __restrict__ b1,
                                             const float* __restrict__ w2,
                                             const float* __restrict__ b2) {
    const int b = blockIdx.x;
    const int c = threadIdx.x;

    __shared__ float s_s[CCH];
    __shared__ float s_h[16];

    float acc = 0.f;
#pragma unroll
    for (int s = 0; s < NS; s++)
        acc += g_partial[((size_t)s * NB + b) * CCH + c];
    s_s[c] = acc * (1.0f / (float)HW);
    __syncthreads();

    if (c < 16) {
        float h = b1[c];
#pragma unroll 8
        for (int k = 0; k < CCH; k++)
            h = fmaf(s_s[k], w1[k * 16 + c], h);
        s_h[c] = fmaxf(h, 0.f);
    }
    __syncthreads();

    float g = b2[c];
#pragma unroll
    for (int j = 0; j < 16; j++)
        g = fmaf(s_h[j], w2[j * CCH + c], g);
    g_gate[b * CCH + c] = 1.f / (1.f + __expf(-g));
}

// ---------------- Pass 3: broadcast multiply ----------------
// One float4 per thread. 32*3136*256/4 = 6,422,528 float4 -> 25088 blocks x 256.
__global__ void __launch_bounds__(256) k_scale(const float* __restrict__ x,
                                               float* __restrict__ out) {
    const int i = blockIdx.x * 256 + threadIdx.x;   // float4 index
    const int c4 = i & (CCH / 4 - 1);
    const int b  = i / (HW * (CCH / 4));

    float4 g = reinterpret_cast<const float4*>(g_gate)[b * (CCH / 4) + c4];
    float4 v = reinterpret_cast<const float4*>(x)[i];
    float4 r = make_float4(v.x * g.x, v.y * g.y, v.z * g.z, v.w * g.w);
    reinterpret_cast<float4*>(out)[i] = r;
}

extern "C" void kernel_launch(void* const* d_in, const int* in_sizes, int n_in,
                              void* d_out, int out_size) {
    const float* x  = (const float*)d_in[0];
    const float* w1 = (const float*)d_in[1];
    const float* b1 = (const float*)d_in[2];
    const float* w2 = (const float*)d_in[3];
    const float* b2 = (const float*)d_in[4];
    float* out = (float*)d_out;

    k_pool<<<dim3(NS, NB), 256>>>(x);
    k_mlp<<<NB, 256>>>(w1, b1, w2, b2);
    const int n4 = NB * HW * (CCH / 4);          // 6,422,528
    k_scale<<<n4 / 256, 256>>>(x, out);
}

// round 2
// speedup vs baseline: 1.2284x; 1.2284x over previous
#include <cuda_runtime.h>
#include <cuda_bf16.h>

// SE block: B=32, H=W=56 (HW=3136), C=256, R=16
#define HW    3136
#define CCH   256
#define NB    32
#define NS    49      // HW chunks in pool pass
#define CHUNK 64      // hw rows per pool block (49*64 = 3136)

// Scratch (allocation-free rule: __device__ globals; zero-initialized at load)
__device__ float g_partial[NS * NB * CCH];   // [s][b][c] partial sums
__device__ float g_gate[NB * CCH];           // sigmoid gate
__device__ unsigned int g_cnt[NB];           // per-batch arrival counters (self-resetting)

// ---------------- Pass 1: partial pool + fused MLP tail ----------------
// grid (NS, NB), 256 threads. Thread t: c4 = t&63 (float4 channel group),
// ho = t>>6 (hw sub-offset 0..3). Each thread accumulates 16 float4 loads.
// Last block to finish for a given batch b computes the mean + excitation MLP.
__global__ void __launch_bounds__(256) k_pool(const float* __restrict__ x,
                                              const float* __restrict__ w1,
                                              const float* __restrict__ b1,
                                              const float* __restrict__ w2,
                                              const float* __restrict__ b2) {
    const int s = blockIdx.x, b = blockIdx.y;
    const int t = threadIdx.x;
    const int c4 = t & 63;
    const int ho = t >> 6;

    const float4* xp = reinterpret_cast<const float4*>(x)
                     + ((size_t)b * HW + (size_t)s * CHUNK + ho) * (CCH / 4) + c4;

    float4 acc = make_float4(0.f, 0.f, 0.f, 0.f);
#pragma unroll
    for (int k = 0; k < CHUNK; k += 4) {
        float4 v = xp[(size_t)k * (CCH / 4)];
        acc.x += v.x; acc.y += v.y; acc.z += v.z; acc.w += v.w;
    }

    __shared__ float4 sm[256];
    __shared__ bool isLast;
    sm[t] = acc;
    __syncthreads();

    if (t < 64) {
        float4 a = sm[t], e = sm[t + 64], f = sm[t + 128], h = sm[t + 192];
        float4 r = make_float4(a.x + e.x + f.x + h.x,
                               a.y + e.y + f.y + h.y,
                               a.z + e.z + f.z + h.z,
                               a.w + e.w + f.w + h.w);
        reinterpret_cast<float4*>(g_partial)[((size_t)s * NB + b) * (CCH / 4) + t] = r;
    }
    __syncthreads();

    // threadfence-reduction handoff: last block per batch runs the MLP
    if (t == 0) {
        __threadfence();
        unsigned int old = atomicAdd(&g_cnt[b], 1u);
        isLast = (old == NS - 1);
    }
    __syncthreads();
    if (!isLast) return;

    if (t == 0) g_cnt[b] = 0;   // reset for next graph replay

    __shared__ float s_s[CCH];
    __shared__ float s_h[16];

    const int c = t;
    float accm = 0.f;
#pragma unroll
    for (int ss = 0; ss < NS; ss++)
        accm += g_partial[((size_t)ss * NB + b) * CCH + c];
    s_s[c] = accm * (1.0f / (float)HW);
    __syncthreads();

    if (c < 16) {
        float h = b1[c];
#pragma unroll 8
        for (int k = 0; k < CCH; k++)
            h = fmaf(s_s[k], w1[k * 16 + c], h);
        s_h[c] = fmaxf(h, 0.f);
    }
    __syncthreads();

    float g = b2[c];
#pragma unroll
    for (int j = 0; j < 16; j++)
        g = fmaf(s_h[j], w2[j * CCH + c], g);
    g_gate[b * CCH + c] = 1.f / (1.f + __expf(-g));
}

// ---------------- Pass 2: broadcast multiply ----------------
// Each block handles 1024 contiguous float4 (4 per thread). Blocks never
// cross a batch boundary (200704 float4 per batch = 196 blocks exactly).
// Reverse block order: earliest-scheduled blocks touch the tail of x, which
// k_pool streamed last -> still hot in L2. Output stored with __stcs
// (evict-first) so the out stream doesn't evict x from L2.
#define SC_NBLK 6272   // 6,422,528 float4 / 1024
__global__ void __launch_bounds__(256) k_scale(const float4* __restrict__ x4,
                                               float4* __restrict__ o4) {
    const int rb = (SC_NBLK - 1) - (int)blockIdx.x;
    const int base = rb * 1024 + (int)threadIdx.x;
    const int b  = rb / 196;            // batch index (196 blocks per batch)
    const int c4 = base & 63;           // channel float4 group (stride 256 keeps it fixed)

    const float4 g = reinterpret_cast<const float4*>(g_gate)[b * 64 + c4];

    float4 v0 = x4[base];
    float4 v1 = x4[base + 256];
    float4 v2 = x4[base + 512];
    float4 v3 = x4[base + 768];

    v0.x *= g.x; v0.y *= g.y; v0.z *= g.z; v0.w *= g.w;
    v1.x *= g.x; v1.y *= g.y; v1.z *= g.z; v1.w *= g.w;
    v2.x *= g.x; v2.y *= g.y; v2.z *= g.z; v2.w *= g.w;
    v3.x *= g.x; v3.y *= g.y; v3.z *= g.z; v3.w *= g.w;

    __stcs(&o4[base],       v0);
    __stcs(&o4[base + 256], v1);
    __stcs(&o4[base + 512], v2);
    __stcs(&o4[base + 768], v3);
}

extern "C" void kernel_launch(void* const* d_in, const int* in_sizes, int n_in,
                              void* d_out, int out_size) {
    const float* x  = (const float*)d_in[0];
    const float* w1 = (const float*)d_in[1];
    const float* b1 = (const float*)d_in[2];
    const float* w2 = (const float*)d_in[3];
    const float* b2 = (const float*)d_in[4];
    float* out = (float*)d_out;

    k_pool<<<dim3(NS, NB), 256>>>(x, w1, b1, w2, b2);
    k_scale<<<SC_NBLK, 256>>>(reinterpret_cast<const float4*>(x),
                              reinterpret_cast<float4*>(out));
}

// round 3
// speedup vs baseline: 1.3695x; 1.1148x over previous
#include <cuda_runtime.h>
#include <cuda_bf16.h>

// SE block: B=32, H=W=56 (HW=3136), C=256, R=16
#define HW     3136
#define CCH    256
#define NB     32
#define NS     49              // hw chunks per batch
#define CHUNK  64              // hw rows per unit
#define NUNIT  (NB * NS)       // 1568 pooling/scale units, u = b*49 + s
#define NBLK   592             // 148 SMs * 4 blocks, all co-resident

// Scratch (__device__ globals per allocation-free rule)
__device__ float g_partial[NUNIT * CCH];   // [u][c]
__device__ float g_gate[NB * CCH];
__device__ unsigned int g_count = 0;       // barrier arrivals (self-resetting)
__device__ unsigned int g_gen   = 0;       // barrier generation (monotonic)

__device__ __forceinline__ void grid_barrier() {
    __syncthreads();
    if (threadIdx.x == 0) {
        unsigned gen = *((volatile unsigned*)&g_gen);
        __threadfence();
        if (atomicAdd(&g_count, 1u) == NBLK - 1) {
            g_count = 0;
            __threadfence();
            atomicAdd(&g_gen, 1u);
        } else {
            while (*((volatile unsigned*)&g_gen) == gen) { }
        }
        __threadfence();
    }
    __syncthreads();
}

__global__ void __launch_bounds__(256, 4)
k_se(const float* __restrict__ x,
     const float* __restrict__ w1,
     const float* __restrict__ b1,
     const float* __restrict__ w2,
     const float* __restrict__ b2,
     float* __restrict__ out) {
    const int bid = blockIdx.x;
    const int t   = threadIdx.x;
    const int c4  = t & 63;        // float4 channel group
    const int ho  = t >> 6;        // hw sub-offset 0..3

    const float4* x4 = reinterpret_cast<const float4*>(x);
    float4*       o4 = reinterpret_cast<float4*>(out);

    __shared__ float4 sm[256];

    // ---------------- Phase 1: partial pooling ----------------
    for (int u = bid; u < NUNIT; u += NBLK) {
        const int b = u / NS, s = u - b * NS;
        const float4* xp = x4 + ((size_t)b * HW + (size_t)s * CHUNK + ho) * (CCH / 4) + c4;

        float4 acc = make_float4(0.f, 0.f, 0.f, 0.f);
#pragma unroll
        for (int k = 0; k < CHUNK; k += 4) {
            float4 v = xp[(size_t)k * (CCH / 4)];
            acc.x += v.x; acc.y += v.y; acc.z += v.z; acc.w += v.w;
        }
        sm[t] = acc;
        __syncthreads();
        if (t < 64) {
            float4 a = sm[t], e = sm[t + 64], f = sm[t + 128], h = sm[t + 192];
            float4 r = make_float4(a.x + e.x + f.x + h.x,
                                   a.y + e.y + f.y + h.y,
                                   a.z + e.z + f.z + h.z,
                                   a.w + e.w + f.w + h.w);
            reinterpret_cast<float4*>(g_partial)[(size_t)u * (CCH / 4) + t] = r;
        }
        __syncthreads();
    }

    grid_barrier();

    // ---------------- Phase MLP: blocks 0..31, one per batch ----------------
    if (bid < NB) {
        const int b = bid;
        const int c = t;
        __shared__ float s_s[CCH];
        __shared__ float s_h[16];
        __shared__ float s_w1[CCH * 16];

        // stage w1 (coalesced, all 256 threads)
#pragma unroll
        for (int i = t; i < CCH * 16; i += 256) s_w1[i] = w1[i];

        float accm = 0.f;
#pragma unroll
        for (int s = 0; s < NS; s++)
            accm += g_partial[((size_t)b * NS + s) * CCH + c];
        s_s[c] = accm * (1.0f / (float)HW);
        __syncthreads();

        if (c < 16) {
            float h = b1[c];
#pragma unroll 8
            for (int k = 0; k < CCH; k++)
                h = fmaf(s_s[k], s_w1[k * 16 + c], h);
            s_h[c] = fmaxf(h, 0.f);
        }
        __syncthreads();

        float g = b2[c];
#pragma unroll
        for (int j = 0; j < 16; j++)
            g = fmaf(s_h[j], w2[j * CCH + c], g);
        g_gate[b * CCH + c] = 1.f / (1.f + __expf(-g));
    }

    grid_barrier();

    // ---------------- Phase 2: broadcast multiply ----------------
    // Same units as phase 1, REVERSE order (last-pooled = hottest in L2).
    const int u_last = bid + ((NUNIT - 1 - bid) / NBLK) * NBLK;
    for (int u = u_last; u >= 0; u -= NBLK) {
        const int b = u / NS, s = u - b * NS;
        const size_t base = ((size_t)b * HW + (size_t)s * CHUNK + ho) * (CCH / 4) + c4;

        const float4 g = reinterpret_cast<const float4*>(g_gate)[b * (CCH / 4) + c4];

#pragma unroll
        for (int k = 0; k < CHUNK; k += 4) {
            const size_t idx = base + (size_t)k * (CCH / 4);
            float4 v = x4[idx];
            v.x *= g.x; v.y *= g.y; v.z *= g.z; v.w *= g.w;
            __stcs(&o4[idx], v);
        }
    }
}

extern "C" void kernel_launch(void* const* d_in, const int* in_sizes, int n_in,
                              void* d_out, int out_size) {
    const float* x  = (const float*)d_in[0];
    const float* w1 = (const float*)d_in[1];
    const float* b1 = (const float*)d_in[2];
    const float* w2 = (const float*)d_in[3];
    const float* b2 = (const float*)d_in[4];
    float* out = (float*)d_out;

    k_se<<<NBLK, 256>>>(x, w1, b1, w2, b2, out);
}